// round 5
// baseline (speedup 1.0000x reference)
#include <cuda_runtime.h>
#include <cuda_bf16.h>
#include <cstdint>

#define T_STEPS 10
#define NN      50000
#define NE      800000

#define BN      128
#define NTHR    256
#define NB_SCAN 196     // ceil(50000/256)

#define S0      52      // A0 row stride (48 cols + pad); 52%32=20 -> conflict-free frags
#define S1      68      // A1 row stride (64 cols + pad); 68%32=4  -> conflict-free frags

// ---------------- device scratch ----------------
__device__ float g_deg [NN];
__device__ float g_dinv[NN];
__device__ float g_xs  [NN * 20];
__device__ float g_acc [NN * 20];
__device__ int   g_off [NN];
__device__ int   g_cur [NN];
__device__ int   g_csrc[NE];
__device__ int   g_bsum[256];
__device__ int   g_btop[256];

// ---------------- prep kernels ----------------
__global__ void k_init() {
    int n = blockIdx.x * blockDim.x + threadIdx.x;
    if (n < NN) { g_deg[n] = 1.0f; g_cur[n] = 0; }
}
__global__ void k_count(const int* __restrict__ ei) {
    int e = blockIdx.x * blockDim.x + threadIdx.x;
    if (e < NE) atomicAdd(&g_deg[ei[NE + e]], 1.0f);
}
__global__ void k_dinv() {
    int n = blockIdx.x * blockDim.x + threadIdx.x;
    if (n < NN) g_dinv[n] = rsqrtf(g_deg[n]);
}
__global__ void k_xs(const float* __restrict__ x) {
    int idx = blockIdx.x * blockDim.x + threadIdx.x;
    if (idx < T_STEPS * NN * 2) {
        int n = (idx >> 1) % NN;
        g_xs[n * 20 + (idx / (NN * 2)) * 2 + (idx & 1)] = g_dinv[n] * x[idx];
    }
}
// ---- CSR build: scan of in-degrees ----
__global__ void k_scan_part() {
    __shared__ int s[256];
    int b = blockIdx.x, tdx = threadIdx.x;
    int n = b * 256 + tdx;
    int v = (n < NN) ? (__float2int_rn(g_deg[n]) - 1) : 0;
    s[tdx] = v;
    __syncthreads();
    for (int d = 1; d < 256; d <<= 1) {
        int tv = (tdx >= d) ? s[tdx - d] : 0;
        __syncthreads();
        s[tdx] += tv;
        __syncthreads();
    }
    if (n < NN) g_off[n] = s[tdx] - v;          // exclusive within block
    if (tdx == 255) g_bsum[b] = s[255];
}
__global__ void k_scan_top() {
    __shared__ int s[256];
    int tdx = threadIdx.x;
    int v = (tdx < NB_SCAN) ? g_bsum[tdx] : 0;
    s[tdx] = v;
    __syncthreads();
    for (int d = 1; d < 256; d <<= 1) {
        int tv = (tdx >= d) ? s[tdx - d] : 0;
        __syncthreads();
        s[tdx] += tv;
        __syncthreads();
    }
    g_btop[tdx] = s[tdx] - v;                    // exclusive
}
__global__ void k_scan_add() {
    int n = blockIdx.x * blockDim.x + threadIdx.x;
    if (n < NN) g_off[n] += g_btop[n >> 8];
}
__global__ void k_fill(const int* __restrict__ ei) {
    int e = blockIdx.x * blockDim.x + threadIdx.x;
    if (e < NE) {
        int d = ei[NE + e];
        int p = atomicAdd(&g_cur[d], 1);
        g_csrc[g_off[d] + p] = ei[e];
    }
}
// ---- pull aggregation: one warp per dst, no float atomics ----
__global__ void k_pull() {
    int gw = (blockIdx.x * blockDim.x + threadIdx.x) >> 5;
    int l  = threadIdx.x & 31;
    if (gw >= NN) return;
    int beg = g_off[gw];
    int num = __float2int_rn(g_deg[gw]) - 1;
    float acc = (l < 20) ? g_xs[gw * 20 + l] : 0.0f;   // self-loop term
    for (int base = 0; base < num; base += 32) {
        int se = (base + l < num) ? g_csrc[beg + base + l] : 0;
        int lim = min(32, num - base);
        for (int j = 0; j < lim; j++) {
            int s = __shfl_sync(0xFFFFFFFFu, se, j);
            if (l < 20) acc += g_xs[s * 20 + l];
        }
    }
    if (l < 20) g_acc[gw * 20 + l] = acc;
}

// ---------------- math helpers ----------------
__device__ __forceinline__ uint32_t tf32b(float x) {
    uint32_t y;
    asm("cvt.rna.tf32.f32 %0, %1;" : "=r"(y) : "f"(x));
    return y;
}
__device__ __forceinline__ void mma_tf32(float d[4], uint32_t a0, uint32_t a1,
                                         uint32_t a2, uint32_t a3,
                                         uint32_t b0, uint32_t b1) {
    asm volatile(
        "mma.sync.aligned.m16n8k8.row.col.f32.tf32.tf32.f32 "
        "{%0,%1,%2,%3}, {%4,%5,%6,%7}, {%8,%9}, {%0,%1,%2,%3};"
        : "+f"(d[0]), "+f"(d[1]), "+f"(d[2]), "+f"(d[3])
        : "r"(a0), "r"(a1), "r"(a2), "r"(a3), "r"(b0), "r"(b1));
}

// smem layout (floats)
#define O_WF0H 0
#define O_WF0L (O_WF0H + 6 * 16 * 64)    // 6144
#define O_WF1H (O_WF0L + 6 * 16 * 64)    // 12288
#define O_WF1L (O_WF1H + 8 * 16 * 64)    // 20480
#define O_BS0  (O_WF1L + 8 * 16 * 64)    // 28672
#define O_BS1  (O_BS0 + 128)
#define O_OW   (O_BS1 + 128)
#define O_GW   (O_OW + 32)
#define O_GB   (O_GW + 32)
#define O_OUTP (O_GB + 16)               // 29008, [128][4]
#define O_XA   (O_OUTP + 512)            // 29520, [10][2][128]
#define O_A0   (O_XA + 2560)             // 32080
#define O_A1   (O_A0 + 128 * S0)         // 38736
#define SM_FLOATS (O_A1 + 128 * S1)      // 47440
#define SM_BYTES  (SM_FLOATS * 4)        // 189760

// split-B tf32 GEMM tile: per warp 4 m-tiles x 4 gate-tiles (interleaved)
__device__ __forceinline__ void gemm_tile(const uint32_t* __restrict__ Abuf,
                                          int strideA, int kks,
                                          const uint32_t* __restrict__ wh,
                                          const uint32_t* __restrict__ wl,
                                          int wr, int wc, int l,
                                          float d[4][4][4]) {
#pragma unroll 2
    for (int kk = 0; kk < kks; kk++) {
        uint32_t a0[4], a1[4], a2[4], a3[4];
#pragma unroll
        for (int mt = 0; mt < 4; mt++) {
            int ab = (wr * 64 + mt * 16 + (l >> 2)) * strideA + kk * 8 + (l & 3);
            a0[mt] = Abuf[ab];
            a1[mt] = Abuf[ab + 8 * strideA];
            a2[mt] = Abuf[ab + 4];
            a3[mt] = Abuf[ab + 8 * strideA + 4];
        }
#pragma unroll
        for (int g = 0; g < 4; g++) {
            uint2 bh = ((const uint2*)wh)[(kk * 16 + wc + 4 * g) * 32 + l];
            uint2 bl = ((const uint2*)wl)[(kk * 16 + wc + 4 * g) * 32 + l];
#pragma unroll
            for (int mt = 0; mt < 4; mt++) {
                mma_tf32(d[mt][g], a0[mt], a1[mt], a2[mt], a3[mt], bh.x, bh.y);
                mma_tf32(d[mt][g], a0[mt], a1[mt], a2[mt], a3[mt], bl.x, bl.y);
            }
        }
    }
}

__global__ __launch_bounds__(NTHR, 1)
void k_main(const float* __restrict__ wih0, const float* __restrict__ whh0,
            const float* __restrict__ bih0, const float* __restrict__ bhh0,
            const float* __restrict__ wih1, const float* __restrict__ whh1,
            const float* __restrict__ bih1, const float* __restrict__ bhh1,
            const float* __restrict__ gw,   const float* __restrict__ gb,
            const float* __restrict__ ow,   const float* __restrict__ ob,
            float* __restrict__ out) {
    extern __shared__ float sm[];
    uint32_t* wf0h = (uint32_t*)(sm + O_WF0H);
    uint32_t* wf0l = (uint32_t*)(sm + O_WF0L);
    uint32_t* wf1h = (uint32_t*)(sm + O_WF1H);
    uint32_t* wf1l = (uint32_t*)(sm + O_WF1L);
    float* bs0  = sm + O_BS0;
    float* bs1  = sm + O_BS1;
    float* ows  = sm + O_OW;
    float* gws  = sm + O_GW;
    float* gbs  = sm + O_GB;
    float* outp = sm + O_OUTP;
    float* xa   = sm + O_XA;
    uint32_t* A0 = (uint32_t*)(sm + O_A0);
    uint32_t* A1 = (uint32_t*)(sm + O_A1);

    int tid = threadIdx.x;
    int node0 = blockIdx.x * BN;

    // ---- prologue: split-tf32 weights in B-fragment order ----
    for (int idx = tid; idx < 6 * 16 * 64; idx += NTHR) {
        int kk = idx >> 10, rem = idx & 1023;
        int j = rem >> 6, ll = (rem >> 1) & 31, half = rem & 1;
        int k = kk * 8 + (ll & 3) + half * 4;
        int c = j * 8 + (ll >> 2);
        float v = (k < 16) ? wih0[c * 16 + k] : whh0[c * 32 + (k - 16)];
        uint32_t hb = tf32b(v);
        wf0h[idx] = hb;
        wf0l[idx] = tf32b(v - __uint_as_float(hb));
    }
    for (int idx = tid; idx < 8 * 16 * 64; idx += NTHR) {
        int kk = idx >> 10, rem = idx & 1023;
        int j = rem >> 6, ll = (rem >> 1) & 31, half = rem & 1;
        int k = kk * 8 + (ll & 3) + half * 4;
        int c = j * 8 + (ll >> 2);
        float v = (k < 32) ? wih1[c * 32 + k] : whh1[c * 32 + (k - 32)];
        uint32_t hb = tf32b(v);
        wf1h[idx] = hb;
        wf1l[idx] = tf32b(v - __uint_as_float(hb));
    }
    if (tid < 128) { bs0[tid] = bih0[tid] + bhh0[tid]; bs1[tid] = bih1[tid] + bhh1[tid]; }
    if (tid < 32) { ows[tid] = ow[tid]; gws[tid] = gw[tid]; }
    if (tid < 16) gbs[tid] = gb[tid];
    for (int idx = tid; idx < 128 * S0; idx += NTHR) A0[idx] = 0u;
    for (int idx = tid; idx < 128 * S1; idx += NTHR) A1[idx] = 0u;

    for (int idx = tid; idx < T_STEPS * 2 * BN; idx += NTHR) {
        int nl = idx & (BN - 1);
        int n = node0 + nl;
        if (n >= NN) n = NN - 1;
        xa[idx] = g_acc[n * 20 + (idx >> 7)] * g_dinv[n];
    }
    __syncthreads();

    // warp grid: wr = node half (0..1), wc = gate column (0..3)
    int w = tid >> 5, l = tid & 31;
    int wr = w >> 2, wc = w & 3;
    int u0 = wc * 8 + 2 * (l & 3);        // units u0, u0+1 owned by this thread

    float c0[16], c1[16];
#pragma unroll
    for (int i = 0; i < 16; i++) { c0[i] = 0.0f; c1[i] = 0.0f; }
    float obv = ob[0];

    for (int t = 0; t < T_STEPS; t++) {
        // ---- GCN ReLU features (tf32) into A0 cols 0..15 ----
        {
            int nl = tid >> 1, f0 = (tid & 1) * 8;
            float x0v = xa[t * 256 + nl];
            float x1v = xa[t * 256 + 128 + nl];
            uint32_t fv[8];
#pragma unroll
            for (int f = 0; f < 8; f++) {
                float v = fmaf(x0v, gws[(f0 + f) * 2],
                          fmaf(x1v, gws[(f0 + f) * 2 + 1], gbs[f0 + f]));
                fv[f] = tf32b(fmaxf(v, 0.0f));
            }
            uint32_t* p = A0 + nl * S0 + f0;
            *(uint4*)(p)     = make_uint4(fv[0], fv[1], fv[2], fv[3]);
            *(uint4*)(p + 4) = make_uint4(fv[4], fv[5], fv[6], fv[7]);
        }
        __syncthreads();   // B1

        // ---- layer0 GEMM ----
        float d[4][4][4];
#pragma unroll
        for (int mt = 0; mt < 4; mt++)
#pragma unroll
            for (int g = 0; g < 4; g++) {
                float b0 = bs0[g * 32 + u0], b1 = bs0[g * 32 + u0 + 1];
                d[mt][g][0] = b0; d[mt][g][1] = b1; d[mt][g][2] = b0; d[mt][g][3] = b1;
            }
        gemm_tile(A0, S0, 6, (uint32_t*)wf0h, (uint32_t*)wf0l, wr, wc, l, d);
        __syncthreads();   // B2

        // ---- layer0 activations; h0 -> A0[16..48], A1[0..32] ----
#pragma unroll
        for (int mt = 0; mt < 4; mt++)
#pragma unroll
            for (int rho = 0; rho < 2; rho++) {
                float cc[2], so[2];
#pragma unroll
                for (int p = 0; p < 2; p++) {
                    int q = 2 * rho + p;
                    float gi = fmaxf(d[mt][0][q], -15.0f);
                    float gf = fmaxf(d[mt][1][q], -15.0f);
                    float gg = fmaxf(d[mt][2][q], -15.0f);
                    float go = fmaxf(d[mt][3][q], -15.0f);
                    float ei = __expf(-gi), ef = __expf(-gf);
                    float eg = __expf(-2.0f * gg), eo = __expf(-go);
                    float Aq = 1.0f + ei, Bq = 1.0f + ef, Cq = 1.0f + eg, Dq = 1.0f + eo;
                    float AB = Aq * Bq, CD = Cq * Dq;
                    float r = __fdividef(1.0f, AB * CD);
                    float si = Bq * CD * r;
                    float sf = Aq * CD * r;
                    so[p]    = AB * Cq * r;
                    float tg = (1.0f - eg) * (AB * Dq) * r;
                    int ci = mt * 4 + rho * 2 + p;
                    cc[p] = sf * c0[ci] + si * tg;
                    c0[ci] = cc[p];
                }
                float e0 = __expf(-2.0f * cc[0]), e1 = __expf(-2.0f * cc[1]);
                float rr = __fdividef(1.0f, (1.0f + e0) * (1.0f + e1));
                float h0v = so[0] * ((1.0f - e0) * (1.0f + e1) * rr);
                float h1v = so[1] * ((1.0f - e1) * (1.0f + e0) * rr);
                int node = wr * 64 + mt * 16 + (l >> 2) + 8 * rho;
                uint32_t hb0 = tf32b(h0v), hb1 = tf32b(h1v);
                A0[node * S0 + 16 + u0]     = hb0;
                A0[node * S0 + 16 + u0 + 1] = hb1;
                A1[node * S1 + u0]          = hb0;
                A1[node * S1 + u0 + 1]      = hb1;
            }
        __syncthreads();   // B3

        // ---- layer1 GEMM ----
#pragma unroll
        for (int mt = 0; mt < 4; mt++)
#pragma unroll
            for (int g = 0; g < 4; g++) {
                float b0 = bs1[g * 32 + u0], b1 = bs1[g * 32 + u0 + 1];
                d[mt][g][0] = b0; d[mt][g][1] = b1; d[mt][g][2] = b0; d[mt][g][3] = b1;
            }
        gemm_tile(A1, S1, 8, (uint32_t*)wf1h, (uint32_t*)wf1l, wr, wc, l, d);
        __syncthreads();   // B4

        // ---- layer1 activations; h1 -> A1[32..64]; fp32 output partials ----
#pragma unroll
        for (int mt = 0; mt < 4; mt++)
#pragma unroll
            for (int rho = 0; rho < 2; rho++) {
                float cc[2], so[2];
#pragma unroll
                for (int p = 0; p < 2; p++) {
                    int q = 2 * rho + p;
                    float gi = fmaxf(d[mt][0][q], -15.0f);
                    float gf = fmaxf(d[mt][1][q], -15.0f);
                    float gg = fmaxf(d[mt][2][q], -15.0f);
                    float go = fmaxf(d[mt][3][q], -15.0f);
                    float ei = __expf(-gi), ef = __expf(-gf);
                    float eg = __expf(-2.0f * gg), eo = __expf(-go);
                    float Aq = 1.0f + ei, Bq = 1.0f + ef, Cq = 1.0f + eg, Dq = 1.0f + eo;
                    float AB = Aq * Bq, CD = Cq * Dq;
                    float r = __fdividef(1.0f, AB * CD);
                    float si = Bq * CD * r;
                    float sf = Aq * CD * r;
                    so[p]    = AB * Cq * r;
                    float tg = (1.0f - eg) * (AB * Dq) * r;
                    int ci = mt * 4 + rho * 2 + p;
                    cc[p] = sf * c1[ci] + si * tg;
                    c1[ci] = cc[p];
                }
                float e0 = __expf(-2.0f * cc[0]), e1 = __expf(-2.0f * cc[1]);
                float rr = __fdividef(1.0f, (1.0f + e0) * (1.0f + e1));
                float h0v = so[0] * ((1.0f - e0) * (1.0f + e1) * rr);
                float h1v = so[1] * ((1.0f - e1) * (1.0f + e0) * rr);
                int node = wr * 64 + mt * 16 + (l >> 2) + 8 * rho;
                A1[node * S1 + 32 + u0]     = tf32b(h0v);
                A1[node * S1 + 32 + u0 + 1] = tf32b(h1v);
                // fp32 output partial over this thread's 2 units
                float po = fmaf(h0v, ows[u0], h1v * ows[u0 + 1]);
                po += __shfl_xor_sync(0xFFFFFFFFu, po, 1);
                po += __shfl_xor_sync(0xFFFFFFFFu, po, 2);
                if ((l & 3) == 0) outp[node * 4 + wc] = po;
            }
        __syncthreads();   // B5

        if (tid < BN) {
            int n = node0 + tid;
            if (n < NN) {
                float s = obv + outp[tid * 4] + outp[tid * 4 + 1]
                              + outp[tid * 4 + 2] + outp[tid * 4 + 3];
                out[t * NN + n] = s;
            }
        }
        // out/outp reads complete before next t's B4; A-buffer reuse guarded by B1/B2
    }
}

// ---------------- launcher ----------------
extern "C" void kernel_launch(void* const* d_in, const int* in_sizes, int n_in,
                              void* d_out, int out_size) {
    const float* x    = (const float*)d_in[0];
    const int*   ei   = (const int*)  d_in[1];
    const float* gw   = (const float*)d_in[2];
    const float* gb   = (const float*)d_in[3];
    const float* wih0 = (const float*)d_in[4];
    const float* whh0 = (const float*)d_in[5];
    const float* bih0 = (const float*)d_in[6];
    const float* bhh0 = (const float*)d_in[7];
    const float* wih1 = (const float*)d_in[8];
    const float* whh1 = (const float*)d_in[9];
    const float* bih1 = (const float*)d_in[10];
    const float* bhh1 = (const float*)d_in[11];
    const float* ow   = (const float*)d_in[12];
    const float* ob   = (const float*)d_in[13];
    float* out = (float*)d_out;

    cudaFuncSetAttribute(k_main, cudaFuncAttributeMaxDynamicSharedMemorySize, SM_BYTES);

    k_init     <<<(NN + 255) / 256, 256>>>();
    k_count    <<<(NE + 255) / 256, 256>>>(ei);
    k_dinv     <<<(NN + 255) / 256, 256>>>();
    k_xs       <<<(T_STEPS * NN * 2 + 255) / 256, 256>>>(x);
    k_scan_part<<<NB_SCAN, 256>>>();
    k_scan_top <<<1, 256>>>();
    k_scan_add <<<(NN + 255) / 256, 256>>>();
    k_fill     <<<(NE + 255) / 256, 256>>>(ei);
    k_pull     <<<(NN * 32 + 255) / 256, 256>>>();
    k_main     <<<(NN + BN - 1) / BN, NTHR, SM_BYTES>>>(
        wih0, whh0, bih0, bhh0, wih1, whh1, bih1, bhh1, gw, gb, ow, ob, out);
}

// round 7
// speedup vs baseline: 1.2832x; 1.2832x over previous
#include <cuda_runtime.h>
#include <cuda_bf16.h>
#include <cstdint>

#define T_STEPS 10
#define NN      50000
#define NE      800000

#define BN      128
#define NTHR    256
#define NB_SCAN 196     // ceil(50000/256)

#define S0      52      // A0 row stride (48 cols + pad); 52%32=20 -> conflict-free frags
#define S1      68      // A1 row stride (64 cols + pad); 68%32=4  -> conflict-free frags

// ---------------- device scratch ----------------
__device__ float g_deg [NN];
__device__ float g_dinv[NN];
__device__ float g_xs  [NN * 20];
__device__ float g_acc [NN * 20];
__device__ int   g_off [NN];
__device__ int   g_cur [NN];
__device__ int   g_csrc[NE];
__device__ int   g_bsum[256];
__device__ int   g_btop[256];

// ---------------- prep kernels ----------------
__global__ void k_init() {
    int n = blockIdx.x * blockDim.x + threadIdx.x;
    if (n < NN) { g_deg[n] = 1.0f; g_cur[n] = 0; }
}
__global__ void k_count(const int* __restrict__ ei) {
    int e = blockIdx.x * blockDim.x + threadIdx.x;
    if (e < NE) atomicAdd(&g_deg[ei[NE + e]], 1.0f);
}
__global__ void k_dinv() {
    int n = blockIdx.x * blockDim.x + threadIdx.x;
    if (n < NN) g_dinv[n] = rsqrtf(g_deg[n]);
}
__global__ void k_xs(const float* __restrict__ x) {
    int idx = blockIdx.x * blockDim.x + threadIdx.x;
    if (idx < T_STEPS * NN * 2) {
        int n = (idx >> 1) % NN;
        g_xs[n * 20 + (idx / (NN * 2)) * 2 + (idx & 1)] = g_dinv[n] * x[idx];
    }
}
// ---- CSR build: scan of in-degrees ----
__global__ void k_scan_part() {
    __shared__ int s[256];
    int b = blockIdx.x, tdx = threadIdx.x;
    int n = b * 256 + tdx;
    int v = (n < NN) ? (__float2int_rn(g_deg[n]) - 1) : 0;
    s[tdx] = v;
    __syncthreads();
    for (int d = 1; d < 256; d <<= 1) {
        int tv = (tdx >= d) ? s[tdx - d] : 0;
        __syncthreads();
        s[tdx] += tv;
        __syncthreads();
    }
    if (n < NN) g_off[n] = s[tdx] - v;
    if (tdx == 255) g_bsum[b] = s[255];
}
__global__ void k_scan_top() {
    __shared__ int s[256];
    int tdx = threadIdx.x;
    int v = (tdx < NB_SCAN) ? g_bsum[tdx] : 0;
    s[tdx] = v;
    __syncthreads();
    for (int d = 1; d < 256; d <<= 1) {
        int tv = (tdx >= d) ? s[tdx - d] : 0;
        __syncthreads();
        s[tdx] += tv;
        __syncthreads();
    }
    g_btop[tdx] = s[tdx] - v;
}
__global__ void k_scan_add() {
    int n = blockIdx.x * blockDim.x + threadIdx.x;
    if (n < NN) g_off[n] += g_btop[n >> 8];
}
__global__ void k_fill(const int* __restrict__ ei) {
    int e = blockIdx.x * blockDim.x + threadIdx.x;
    if (e < NE) {
        int d = ei[NE + e];
        int p = atomicAdd(&g_cur[d], 1);
        g_csrc[g_off[d] + p] = ei[e];
    }
}
// ---- pull aggregation: one warp per dst, no float atomics ----
__global__ void k_pull() {
    int gw = (blockIdx.x * blockDim.x + threadIdx.x) >> 5;
    int l  = threadIdx.x & 31;
    if (gw >= NN) return;
    int beg = g_off[gw];
    int num = __float2int_rn(g_deg[gw]) - 1;
    float acc = (l < 20) ? g_xs[gw * 20 + l] : 0.0f;   // self-loop term
    for (int base = 0; base < num; base += 32) {
        int se = (base + l < num) ? g_csrc[beg + base + l] : 0;
        int lim = min(32, num - base);
        for (int j = 0; j < lim; j++) {
            int s = __shfl_sync(0xFFFFFFFFu, se, j);
            if (l < 20) acc += g_xs[s * 20 + l];
        }
    }
    if (l < 20) g_acc[gw * 20 + l] = acc;
}

// ---------------- math helpers ----------------
__device__ __forceinline__ uint32_t tf32b(float x) {
    uint32_t y;
    asm("cvt.rna.tf32.f32 %0, %1;" : "=r"(y) : "f"(x));
    return y;
}
__device__ __forceinline__ void mma_tf32(float d[4], uint32_t a0, uint32_t a1,
                                         uint32_t a2, uint32_t a3,
                                         uint32_t b0, uint32_t b1) {
    asm volatile(
        "mma.sync.aligned.m16n8k8.row.col.f32.tf32.tf32.f32 "
        "{%0,%1,%2,%3}, {%4,%5,%6,%7}, {%8,%9}, {%0,%1,%2,%3};"
        : "+f"(d[0]), "+f"(d[1]), "+f"(d[2]), "+f"(d[3])
        : "r"(a0), "r"(a1), "r"(a2), "r"(a3), "r"(b0), "r"(b1));
}
// exact LSTM cell update via grouped reciprocal: 4 exp + 1 rcp
__device__ __forceinline__ void cell_update(float gi, float gf, float gg, float go,
                                            float& c, float& so) {
    gi = fmaxf(gi, -15.0f);
    gf = fmaxf(gf, -15.0f);
    gg = fmaxf(gg, -15.0f);
    go = fmaxf(go, -15.0f);
    float ei = __expf(-gi), ef = __expf(-gf);
    float eg = __expf(-2.0f * gg), eo = __expf(-go);
    float Aq = 1.0f + ei, Bq = 1.0f + ef, Cq = 1.0f + eg, Dq = 1.0f + eo;
    float AB = Aq * Bq, CD = Cq * Dq;
    float r = __fdividef(1.0f, AB * CD);
    float si = Bq * CD * r;                 // sigma(i)
    float sf = Aq * CD * r;                 // sigma(f)
    so       = AB * Cq * r;                 // sigma(o)
    float tg = (1.0f - eg) * (AB * Dq) * r; // tanh(g)
    c = sf * c + si * tg;
}
// shared tanh for a pair of cell states: 2 exp + 1 rcp
__device__ __forceinline__ void tanh_pair(float cA, float cB, float& tA, float& tB) {
    float e0 = __expf(-2.0f * cA), e1 = __expf(-2.0f * cB);
    float rr = __fdividef(1.0f, (1.0f + e0) * (1.0f + e1));
    tA = (1.0f - e0) * (1.0f + e1) * rr;
    tB = (1.0f - e1) * (1.0f + e0) * rr;
}

// smem layout (floats) — identical to R4
#define O_WF0 0                          // [6 kk][16 j][32 lane][2]
#define O_WF1 (O_WF0 + 6 * 16 * 64)      // 6144
#define O_BS0 (O_WF1 + 8 * 16 * 64)      // 14336
#define O_BS1 (O_BS0 + 128)
#define O_OW  (O_BS1 + 128)
#define O_GW  (O_OW + 32)
#define O_GB  (O_GW + 32)
#define O_XA  (O_GB + 16)                // [10][2][128]
#define O_A0  (O_XA + T_STEPS * 2 * 128)
#define O_A1  (O_A0 + 128 * S0)
#define SM_FLOATS (O_A1 + 128 * S1)
#define SM_BYTES  (SM_FLOATS * 4)        // 130368

__global__ __launch_bounds__(NTHR, 1)
void k_main(const float* __restrict__ wih0, const float* __restrict__ whh0,
            const float* __restrict__ bih0, const float* __restrict__ bhh0,
            const float* __restrict__ wih1, const float* __restrict__ whh1,
            const float* __restrict__ bih1, const float* __restrict__ bhh1,
            const float* __restrict__ gw,   const float* __restrict__ gb,
            const float* __restrict__ ow,   const float* __restrict__ ob,
            float* __restrict__ out) {
    extern __shared__ float sm[];
    uint32_t* wf0 = (uint32_t*)(sm + O_WF0);
    uint32_t* wf1 = (uint32_t*)(sm + O_WF1);
    float* bs0 = sm + O_BS0;
    float* bs1 = sm + O_BS1;
    float* ows = sm + O_OW;
    float* gws = sm + O_GW;
    float* gbs = sm + O_GB;
    float* xa  = sm + O_XA;
    uint32_t* A0 = (uint32_t*)(sm + O_A0);
    uint32_t* A1 = (uint32_t*)(sm + O_A1);

    int tid = threadIdx.x;
    int node0 = blockIdx.x * BN;

    // ---- prologue: weights in B-fragment order (tf32) ----
    for (int idx = tid; idx < 6 * 16 * 64; idx += NTHR) {
        int kk = idx >> 10, rem = idx & 1023;
        int j = rem >> 6, ll = (rem >> 1) & 31, half = rem & 1;
        int k = kk * 8 + (ll & 3) + half * 4;
        int c = j * 8 + (ll >> 2);
        float v = (k < 16) ? wih0[c * 16 + k] : whh0[c * 32 + (k - 16)];
        wf0[idx] = tf32b(v);
    }
    for (int idx = tid; idx < 8 * 16 * 64; idx += NTHR) {
        int kk = idx >> 10, rem = idx & 1023;
        int j = rem >> 6, ll = (rem >> 1) & 31, half = rem & 1;
        int k = kk * 8 + (ll & 3) + half * 4;
        int c = j * 8 + (ll >> 2);
        float v = (k < 32) ? wih1[c * 32 + k] : whh1[c * 32 + (k - 32)];
        wf1[idx] = tf32b(v);
    }
    if (tid < 128) { bs0[tid] = bih0[tid] + bhh0[tid]; bs1[tid] = bih1[tid] + bhh1[tid]; }
    if (tid < 32) { ows[tid] = ow[tid]; gws[tid] = gw[tid]; }
    if (tid < 16) gbs[tid] = gb[tid];
    for (int idx = tid; idx < 128 * S0; idx += NTHR) A0[idx] = 0u;
    for (int idx = tid; idx < 128 * S1; idx += NTHR) A1[idx] = 0u;

    for (int idx = tid; idx < T_STEPS * 2 * BN; idx += NTHR) {
        int nl = idx & (BN - 1);
        int n = node0 + nl;
        if (n >= NN) n = NN - 1;
        xa[idx] = g_acc[n * 20 + (idx >> 7)] * g_dinv[n];
    }
    __syncthreads();

    // ---- warp/lane geometry (R4) ----
    int w = tid >> 5;
    int l = tid & 31;
    int r0 = w * 16 + (l >> 2);
    int cb = 2 * (l & 3);

    float c0[16], c1[16];
#pragma unroll
    for (int i = 0; i < 16; i++) { c0[i] = 0.0f; c1[i] = 0.0f; }
    float obv = ob[0];

    for (int t = 0; t < T_STEPS; t++) {
        // ---- GCN ReLU features (tf32) into A0 cols 0..15 ----
        {
            int nl = tid >> 1, f0 = (tid & 1) * 8;
            float x0v = xa[t * 256 + nl];
            float x1v = xa[t * 256 + 128 + nl];
            uint32_t fv[8];
#pragma unroll
            for (int f = 0; f < 8; f++) {
                float v = fmaf(x0v, gws[(f0 + f) * 2],
                          fmaf(x1v, gws[(f0 + f) * 2 + 1], gbs[f0 + f]));
                fv[f] = tf32b(fmaxf(v, 0.0f));
            }
            uint32_t* p = A0 + nl * S0 + f0;
            *(uint4*)(p)     = make_uint4(fv[0], fv[1], fv[2], fv[3]);
            *(uint4*)(p + 4) = make_uint4(fv[4], fv[5], fv[6], fv[7]);
        }
        __syncthreads();   // B1

        // ---- layer0 GEMM: [16 nodes] x [128 gates] x K=48 ----
        float d[16][4];
#pragma unroll
        for (int j = 0; j < 16; j++) {
            float b0v = bs0[j * 8 + cb], b1v = bs0[j * 8 + cb + 1];
            d[j][0] = b0v; d[j][1] = b1v; d[j][2] = b0v; d[j][3] = b1v;
        }
#pragma unroll
        for (int kk = 0; kk < 6; kk++) {
            int ab = r0 * S0 + kk * 8 + (l & 3);
            uint32_t a0 = A0[ab], a1 = A0[ab + 8 * S0];
            uint32_t a2 = A0[ab + 4], a3 = A0[ab + 8 * S0 + 4];
            const uint2* bp = (const uint2*)wf0 + kk * 16 * 32 + l;
#pragma unroll
            for (int j = 0; j < 16; j++) {
                uint2 b = bp[j * 32];
                mma_tf32(d[j], a0, a1, a2, a3, b.x, b.y);
            }
        }
        __syncthreads();   // B2

        // ---- layer0 activations (exact); h0 -> A0[16..48], A1[0..32] ----
#pragma unroll
        for (int m = 0; m < 4; m++)
#pragma unroll
            for (int rho = 0; rho < 2; rho++) {
                int q0 = 2 * rho, q1 = 2 * rho + 1;
                int ci0 = (m * 2 + rho) * 2, ci1 = ci0 + 1;
                float soA, soB;
                cell_update(d[0 + m][q0], d[4 + m][q0], d[8 + m][q0], d[12 + m][q0],
                            c0[ci0], soA);
                cell_update(d[0 + m][q1], d[4 + m][q1], d[8 + m][q1], d[12 + m][q1],
                            c0[ci1], soB);
                float tA, tB;
                tanh_pair(c0[ci0], c0[ci1], tA, tB);
                float hA = soA * tA, hB = soB * tB;
                int u = 8 * m + cb;
                int node = r0 + 8 * rho;
                uint32_t hb0 = tf32b(hA), hb1 = tf32b(hB);
                A0[node * S0 + 16 + u]     = hb0;
                A0[node * S0 + 16 + u + 1] = hb1;
                A1[node * S1 + u]          = hb0;
                A1[node * S1 + u + 1]      = hb1;
            }
        __syncthreads();   // B3

        // ---- layer1 GEMM: K=64 ----
#pragma unroll
        for (int j = 0; j < 16; j++) {
            float b0v = bs1[j * 8 + cb], b1v = bs1[j * 8 + cb + 1];
            d[j][0] = b0v; d[j][1] = b1v; d[j][2] = b0v; d[j][3] = b1v;
        }
#pragma unroll
        for (int kk = 0; kk < 8; kk++) {
            int ab = r0 * S1 + kk * 8 + (l & 3);
            uint32_t a0 = A1[ab], a1 = A1[ab + 8 * S1];
            uint32_t a2 = A1[ab + 4], a3 = A1[ab + 8 * S1 + 4];
            const uint2* bp = (const uint2*)wf1 + kk * 16 * 32 + l;
#pragma unroll
            for (int j = 0; j < 16; j++) {
                uint2 b = bp[j * 32];
                mma_tf32(d[j], a0, a1, a2, a3, b.x, b.y);
            }
        }
        __syncthreads();   // B4

        // ---- layer1 activations (exact); h1 -> A1[32..64]; fused out proj ----
        float po0 = 0.0f, po1 = 0.0f;
#pragma unroll
        for (int m = 0; m < 4; m++)
#pragma unroll
            for (int rho = 0; rho < 2; rho++) {
                int q0 = 2 * rho, q1 = 2 * rho + 1;
                int ci0 = (m * 2 + rho) * 2, ci1 = ci0 + 1;
                float soA, soB;
                cell_update(d[0 + m][q0], d[4 + m][q0], d[8 + m][q0], d[12 + m][q0],
                            c1[ci0], soA);
                cell_update(d[0 + m][q1], d[4 + m][q1], d[8 + m][q1], d[12 + m][q1],
                            c1[ci1], soB);
                float tA, tB;
                tanh_pair(c1[ci0], c1[ci1], tA, tB);
                float hA = soA * tA, hB = soB * tB;
                int u = 8 * m + cb;
                int node = r0 + 8 * rho;
                A1[node * S1 + 32 + u]     = tf32b(hA);
                A1[node * S1 + 32 + u + 1] = tf32b(hB);
                float hw = fmaf(hA, ows[u], hB * ows[u + 1]);
                if (rho == 0) po0 += hw; else po1 += hw;
            }
        po0 += __shfl_xor_sync(0xFFFFFFFFu, po0, 1);
        po0 += __shfl_xor_sync(0xFFFFFFFFu, po0, 2);
        po1 += __shfl_xor_sync(0xFFFFFFFFu, po1, 1);
        po1 += __shfl_xor_sync(0xFFFFFFFFu, po1, 2);
        if ((l & 3) == 0) {
            int n0 = node0 + r0;
            if (n0 < NN) out[t * NN + n0] = po0 + obv;
            int n1 = node0 + r0 + 8;
            if (n1 < NN) out[t * NN + n1] = po1 + obv;
        }
    }
}

// ---------------- launcher ----------------
extern "C" void kernel_launch(void* const* d_in, const int* in_sizes, int n_in,
                              void* d_out, int out_size) {
    const float* x    = (const float*)d_in[0];
    const int*   ei   = (const int*)  d_in[1];
    const float* gw   = (const float*)d_in[2];
    const float* gb   = (const float*)d_in[3];
    const float* wih0 = (const float*)d_in[4];
    const float* whh0 = (const float*)d_in[5];
    const float* bih0 = (const float*)d_in[6];
    const float* bhh0 = (const float*)d_in[7];
    const float* wih1 = (const float*)d_in[8];
    const float* whh1 = (const float*)d_in[9];
    const float* bih1 = (const float*)d_in[10];
    const float* bhh1 = (const float*)d_in[11];
    const float* ow   = (const float*)d_in[12];
    const float* ob   = (const float*)d_in[13];
    float* out = (float*)d_out;

    cudaFuncSetAttribute(k_main, cudaFuncAttributeMaxDynamicSharedMemorySize, SM_BYTES);

    k_init     <<<(NN + 255) / 256, 256>>>();
    k_count    <<<(NE + 255) / 256, 256>>>(ei);
    k_dinv     <<<(NN + 255) / 256, 256>>>();
    k_xs       <<<(T_STEPS * NN * 2 + 255) / 256, 256>>>(x);
    k_scan_part<<<NB_SCAN, 256>>>();
    k_scan_top <<<1, 256>>>();
    k_scan_add <<<(NN + 255) / 256, 256>>>();
    k_fill     <<<(NE + 255) / 256, 256>>>(ei);
    k_pull     <<<(NN * 32 + 255) / 256, 256>>>();
    k_main     <<<(NN + BN - 1) / BN, NTHR, SM_BYTES>>>(
        wih0, whh0, bih0, bhh0, wih1, whh1, bih1, bhh1, gw, gb, ow, ob, out);
}

// round 9
// speedup vs baseline: 1.6546x; 1.2895x over previous
#include <cuda_runtime.h>
#include <cuda_bf16.h>
#include <cstdint>

#define T_STEPS 10
#define NN      50000
#define NE      800000

#define BN      128
#define NTHR    256
#define NB_SCAN 196     // ceil(50000/256)

#define S0      52      // A0 row stride (48 cols + pad); 52%32=20 -> conflict-free frags
#define S1      68      // A1 row stride (64 cols + pad); 68%32=4  -> conflict-free frags

// ---------------- device scratch ----------------
__device__ float g_deg [NN];
__device__ float g_dinv[NN];
__device__ float g_xs  [NN * 20];
__device__ float g_acc [NN * 20];
__device__ int   g_off [NN];
__device__ int   g_cur [NN];
__device__ int   g_csrc[NE];
__device__ int   g_bsum[256];
__device__ int   g_btop[256];

// ---------------- prep kernels ----------------
__global__ void k_init() {
    int n = blockIdx.x * blockDim.x + threadIdx.x;
    if (n < NN) { g_deg[n] = 1.0f; g_cur[n] = 0; }
}
__global__ void k_count(const int* __restrict__ ei) {
    int e = blockIdx.x * blockDim.x + threadIdx.x;
    if (e < NE) atomicAdd(&g_deg[ei[NE + e]], 1.0f);
}
__global__ void k_dinv() {
    int n = blockIdx.x * blockDim.x + threadIdx.x;
    if (n < NN) g_dinv[n] = rsqrtf(g_deg[n]);
}
__global__ void k_xs(const float* __restrict__ x) {
    int idx = blockIdx.x * blockDim.x + threadIdx.x;
    if (idx < T_STEPS * NN * 2) {
        int n = (idx >> 1) % NN;
        g_xs[n * 20 + (idx / (NN * 2)) * 2 + (idx & 1)] = g_dinv[n] * x[idx];
    }
}
// ---- CSR build: scan of in-degrees ----
__global__ void k_scan_part() {
    __shared__ int s[256];
    int b = blockIdx.x, tdx = threadIdx.x;
    int n = b * 256 + tdx;
    int v = (n < NN) ? (__float2int_rn(g_deg[n]) - 1) : 0;
    s[tdx] = v;
    __syncthreads();
    for (int d = 1; d < 256; d <<= 1) {
        int tv = (tdx >= d) ? s[tdx - d] : 0;
        __syncthreads();
        s[tdx] += tv;
        __syncthreads();
    }
    if (n < NN) g_off[n] = s[tdx] - v;
    if (tdx == 255) g_bsum[b] = s[255];
}
__global__ void k_scan_top() {
    __shared__ int s[256];
    int tdx = threadIdx.x;
    int v = (tdx < NB_SCAN) ? g_bsum[tdx] : 0;
    s[tdx] = v;
    __syncthreads();
    for (int d = 1; d < 256; d <<= 1) {
        int tv = (tdx >= d) ? s[tdx - d] : 0;
        __syncthreads();
        s[tdx] += tv;
        __syncthreads();
    }
    g_btop[tdx] = s[tdx] - v;
}
__global__ void k_scan_add() {
    int n = blockIdx.x * blockDim.x + threadIdx.x;
    if (n < NN) g_off[n] += g_btop[n >> 8];
}
__global__ void k_fill(const int* __restrict__ ei) {
    int e = blockIdx.x * blockDim.x + threadIdx.x;
    if (e < NE) {
        int d = ei[NE + e];
        int p = atomicAdd(&g_cur[d], 1);
        g_csrc[g_off[d] + p] = ei[e];
    }
}
// ---- pull aggregation: one warp per dst, no float atomics ----
__global__ void k_pull() {
    int gw = (blockIdx.x * blockDim.x + threadIdx.x) >> 5;
    int l  = threadIdx.x & 31;
    if (gw >= NN) return;
    int beg = g_off[gw];
    int num = __float2int_rn(g_deg[gw]) - 1;
    float acc = (l < 20) ? g_xs[gw * 20 + l] : 0.0f;   // self-loop term
    for (int base = 0; base < num; base += 32) {
        int se = (base + l < num) ? g_csrc[beg + base + l] : 0;
        int lim = min(32, num - base);
        for (int j = 0; j < lim; j++) {
            int s = __shfl_sync(0xFFFFFFFFu, se, j);
            if (l < 20) acc += g_xs[s * 20 + l];
        }
    }
    if (l < 20) g_acc[gw * 20 + l] = acc;
}

// ---------------- math helpers ----------------
__device__ __forceinline__ float tanhap(float x) {
    float y;
    asm("tanh.approx.f32 %0, %1;" : "=f"(y) : "f"(x));
    return y;
}
__device__ __forceinline__ float sigf(float x) {
    return fmaf(tanhap(0.5f * x), 0.5f, 0.5f);
}
__device__ __forceinline__ uint32_t tf32b(float x) {
    uint32_t y;
    asm("cvt.rna.tf32.f32 %0, %1;" : "=r"(y) : "f"(x));
    return y;
}
__device__ __forceinline__ void mma_tf32(float d[4], uint32_t a0, uint32_t a1,
                                         uint32_t a2, uint32_t a3,
                                         uint32_t b0, uint32_t b1) {
    asm volatile(
        "mma.sync.aligned.m16n8k8.row.col.f32.tf32.tf32.f32 "
        "{%0,%1,%2,%3}, {%4,%5,%6,%7}, {%8,%9}, {%0,%1,%2,%3};"
        : "+f"(d[0]), "+f"(d[1]), "+f"(d[2]), "+f"(d[3])
        : "r"(a0), "r"(a1), "r"(a2), "r"(a3), "r"(b0), "r"(b1));
}

// smem layout (floats) — identical to R4
#define O_WF0 0                          // [6 kk][16 j][32 lane][2]
#define O_WF1 (O_WF0 + 6 * 16 * 64)      // 6144
#define O_BS0 (O_WF1 + 8 * 16 * 64)      // 14336
#define O_BS1 (O_BS0 + 128)
#define O_OW  (O_BS1 + 128)
#define O_GW  (O_OW + 32)
#define O_GB  (O_GW + 32)
#define O_XA  (O_GB + 16)                // [10][2][128]
#define O_A0  (O_XA + T_STEPS * 2 * 128)
#define O_A1  (O_A0 + 128 * S0)
#define SM_FLOATS (O_A1 + 128 * S1)
#define SM_BYTES  (SM_FLOATS * 4)        // 130368

__global__ __launch_bounds__(NTHR, 1)
void k_main(const float* __restrict__ wih0, const float* __restrict__ whh0,
            const float* __restrict__ bih0, const float* __restrict__ bhh0,
            const float* __restrict__ wih1, const float* __restrict__ whh1,
            const float* __restrict__ bih1, const float* __restrict__ bhh1,
            const float* __restrict__ gw,   const float* __restrict__ gb,
            const float* __restrict__ ow,   const float* __restrict__ ob,
            float* __restrict__ out) {
    extern __shared__ float sm[];
    uint32_t* wf0 = (uint32_t*)(sm + O_WF0);
    uint32_t* wf1 = (uint32_t*)(sm + O_WF1);
    float* bs0 = sm + O_BS0;
    float* bs1 = sm + O_BS1;
    float* ows = sm + O_OW;
    float* gws = sm + O_GW;
    float* gbs = sm + O_GB;
    float* xa  = sm + O_XA;
    uint32_t* A0 = (uint32_t*)(sm + O_A0);
    uint32_t* A1 = (uint32_t*)(sm + O_A1);

    int tid = threadIdx.x;
    int node0 = blockIdx.x * BN;

    // ---- prologue: weights in B-fragment order (tf32) ----
    for (int idx = tid; idx < 6 * 16 * 64; idx += NTHR) {
        int kk = idx >> 10, rem = idx & 1023;
        int j = rem >> 6, ll = (rem >> 1) & 31, half = rem & 1;
        int k = kk * 8 + (ll & 3) + half * 4;
        int c = j * 8 + (ll >> 2);                 // torch gate order i,f,g,o
        float v = (k < 16) ? wih0[c * 16 + k] : whh0[c * 32 + (k - 16)];
        wf0[idx] = tf32b(v);
    }
    for (int idx = tid; idx < 8 * 16 * 64; idx += NTHR) {
        int kk = idx >> 10, rem = idx & 1023;
        int j = rem >> 6, ll = (rem >> 1) & 31, half = rem & 1;
        int k = kk * 8 + (ll & 3) + half * 4;
        int c = j * 8 + (ll >> 2);
        float v = (k < 32) ? wih1[c * 32 + k] : whh1[c * 32 + (k - 32)];
        wf1[idx] = tf32b(v);
    }
    if (tid < 128) { bs0[tid] = bih0[tid] + bhh0[tid]; bs1[tid] = bih1[tid] + bhh1[tid]; }
    if (tid < 32) { ows[tid] = ow[tid]; gws[tid] = gw[tid]; }
    if (tid < 16) gbs[tid] = gb[tid];
    for (int idx = tid; idx < 128 * S0; idx += NTHR) A0[idx] = 0u;
    for (int idx = tid; idx < 128 * S1; idx += NTHR) A1[idx] = 0u;

    for (int idx = tid; idx < T_STEPS * 2 * BN; idx += NTHR) {
        int nl = idx & (BN - 1);
        int n = node0 + nl;
        if (n >= NN) n = NN - 1;
        xa[idx] = g_acc[n * 20 + (idx >> 7)] * g_dinv[n];
    }
    __syncthreads();

    // ---- warp/lane geometry (R4) ----
    int w = tid >> 5;
    int l = tid & 31;
    int r0 = w * 16 + (l >> 2);
    int cb = 2 * (l & 3);

    float c0[16], c1[16];
#pragma unroll
    for (int i = 0; i < 16; i++) { c0[i] = 0.0f; c1[i] = 0.0f; }
    float obv = ob[0];

    for (int t = 0; t < T_STEPS; t++) {
        // ---- GCN ReLU features (tf32) into A0 cols 0..15 ----
        {
            int nl = tid >> 1, f0 = (tid & 1) * 8;
            float x0v = xa[t * 256 + nl];
            float x1v = xa[t * 256 + 128 + nl];
            uint32_t fv[8];
#pragma unroll
            for (int f = 0; f < 8; f++) {
                float v = fmaf(x0v, gws[(f0 + f) * 2],
                          fmaf(x1v, gws[(f0 + f) * 2 + 1], gbs[f0 + f]));
                fv[f] = tf32b(fmaxf(v, 0.0f));
            }
            uint32_t* p = A0 + nl * S0 + f0;
            *(uint4*)(p)     = make_uint4(fv[0], fv[1], fv[2], fv[3]);
            *(uint4*)(p + 4) = make_uint4(fv[4], fv[5], fv[6], fv[7]);
        }
        __syncthreads();   // B1

        // ---- layer0 GEMM: [16 nodes] x [128 gates] x K=48 ----
        float d[16][4];
#pragma unroll
        for (int j = 0; j < 16; j++) {
            float b0v = bs0[j * 8 + cb], b1v = bs0[j * 8 + cb + 1];
            d[j][0] = b0v; d[j][1] = b1v; d[j][2] = b0v; d[j][3] = b1v;
        }
#pragma unroll
        for (int kk = 0; kk < 6; kk++) {
            int ab = r0 * S0 + kk * 8 + (l & 3);
            uint32_t a0 = A0[ab], a1 = A0[ab + 8 * S0];
            uint32_t a2 = A0[ab + 4], a3 = A0[ab + 8 * S0 + 4];
            const uint2* bp = (const uint2*)wf0 + kk * 16 * 32 + l;
#pragma unroll
            for (int j = 0; j < 16; j++) {
                uint2 b = bp[j * 32];
                mma_tf32(d[j], a0, a1, a2, a3, b.x, b.y);
            }
        }
        __syncthreads();   // B2

        // ---- layer0 activations (approx); h0 -> A0[16..48], A1[0..32] ----
#pragma unroll
        for (int m = 0; m < 4; m++)
#pragma unroll
            for (int rho = 0; rho < 2; rho++)
#pragma unroll
                for (int p = 0; p < 2; p++) {
                    int q = 2 * rho + p;
                    int ci = (m * 2 + rho) * 2 + p;
                    float gi = d[0 + m][q],  gf = d[4 + m][q];
                    float gg = d[8 + m][q],  go = d[12 + m][q];
                    float cc = sigf(gf) * c0[ci] + sigf(gi) * tanhap(gg);
                    c0[ci] = cc;
                    float h = sigf(go) * tanhap(cc);
                    int u = 8 * m + cb + p;
                    int node = r0 + 8 * rho;
                    uint32_t hb = tf32b(h);
                    A0[node * S0 + 16 + u] = hb;
                    A1[node * S1 + u]      = hb;
                }
        __syncthreads();   // B3

        // ---- layer1 GEMM: K=64 ----
#pragma unroll
        for (int j = 0; j < 16; j++) {
            float b0v = bs1[j * 8 + cb], b1v = bs1[j * 8 + cb + 1];
            d[j][0] = b0v; d[j][1] = b1v; d[j][2] = b0v; d[j][3] = b1v;
        }
#pragma unroll
        for (int kk = 0; kk < 8; kk++) {
            int ab = r0 * S1 + kk * 8 + (l & 3);
            uint32_t a0 = A1[ab], a1 = A1[ab + 8 * S1];
            uint32_t a2 = A1[ab + 4], a3 = A1[ab + 8 * S1 + 4];
            const uint2* bp = (const uint2*)wf1 + kk * 16 * 32 + l;
#pragma unroll
            for (int j = 0; j < 16; j++) {
                uint2 b = bp[j * 32];
                mma_tf32(d[j], a0, a1, a2, a3, b.x, b.y);
            }
        }
        __syncthreads();   // B4

        // ---- layer1 activations (approx); h1 -> A1[32..64]; fused out proj ----
        float po0 = 0.0f, po1 = 0.0f;
#pragma unroll
        for (int m = 0; m < 4; m++)
#pragma unroll
            for (int rho = 0; rho < 2; rho++)
#pragma unroll
                for (int p = 0; p < 2; p++) {
                    int q = 2 * rho + p;
                    int ci = (m * 2 + rho) * 2 + p;
                    float gi = d[0 + m][q],  gf = d[4 + m][q];
                    float gg = d[8 + m][q],  go = d[12 + m][q];
                    float cc = sigf(gf) * c1[ci] + sigf(gi) * tanhap(gg);
                    c1[ci] = cc;
                    float h = sigf(go) * tanhap(cc);
                    int u = 8 * m + cb + p;
                    int node = r0 + 8 * rho;
                    A1[node * S1 + 32 + u] = tf32b(h);
                    float hw = h * ows[u];
                    if (rho == 0) po0 += hw; else po1 += hw;
                }
        po0 += __shfl_xor_sync(0xFFFFFFFFu, po0, 1);
        po0 += __shfl_xor_sync(0xFFFFFFFFu, po0, 2);
        po1 += __shfl_xor_sync(0xFFFFFFFFu, po1, 1);
        po1 += __shfl_xor_sync(0xFFFFFFFFu, po1, 2);
        if ((l & 3) == 0) {
            int n0 = node0 + r0;
            if (n0 < NN) out[t * NN + n0] = po0 + obv;
            int n1 = node0 + r0 + 8;
            if (n1 < NN) out[t * NN + n1] = po1 + obv;
        }
    }
}

// ---------------- launcher ----------------
extern "C" void kernel_launch(void* const* d_in, const int* in_sizes, int n_in,
                              void* d_out, int out_size) {
    const float* x    = (const float*)d_in[0];
    const int*   ei   = (const int*)  d_in[1];
    const float* gw   = (const float*)d_in[2];
    const float* gb   = (const float*)d_in[3];
    const float* wih0 = (const float*)d_in[4];
    const float* whh0 = (const float*)d_in[5];
    const float* bih0 = (const float*)d_in[6];
    const float* bhh0 = (const float*)d_in[7];
    const float* wih1 = (const float*)d_in[8];
    const float* whh1 = (const float*)d_in[9];
    const float* bih1 = (const float*)d_in[10];
    const float* bhh1 = (const float*)d_in[11];
    const float* ow   = (const float*)d_in[12];
    const float* ob   = (const float*)d_in[13];
    float* out = (float*)d_out;

    cudaFuncSetAttribute(k_main, cudaFuncAttributeMaxDynamicSharedMemorySize, SM_BYTES);

    k_init     <<<(NN + 255) / 256, 256>>>();
    k_count    <<<(NE + 255) / 256, 256>>>(ei);
    k_dinv     <<<(NN + 255) / 256, 256>>>();
    k_xs       <<<(T_STEPS * NN * 2 + 255) / 256, 256>>>(x);
    k_scan_part<<<NB_SCAN, 256>>>();
    k_scan_top <<<1, 256>>>();
    k_scan_add <<<(NN + 255) / 256, 256>>>();
    k_fill     <<<(NE + 255) / 256, 256>>>(ei);
    k_pull     <<<(NN * 32 + 255) / 256, 256>>>();
    k_main     <<<(NN + BN - 1) / BN, NTHR, SM_BYTES>>>(
        wih0, whh0, bih0, bhh0, wih1, whh1, bih1, bhh1, gw, gb, ow, ob, out);
}